// round 1
// baseline (speedup 1.0000x reference)
#include <cuda_runtime.h>

#define NV 4096
#define F1 512
#define FH 256
#define NHEADS 4
#define F2 1024   // nhid * nheads
#define FO 256
#define NW (NV/32) // 128 bitmask words per row

// ---------------- scratch (static device memory; no allocations) ------------
__device__ __align__(16) float g_Wh1[NHEADS * NV * FH]; // 16 MB
__device__ __align__(16) float g_h1[NV * F2];           // 16 MB
__device__ __align__(16) float g_Wh2[NV * FO];          // 4 MB
__device__ __align__(16) float g_src1[NHEADS * NV];
__device__ __align__(16) float g_dst1[NHEADS * NV];
__device__ __align__(16) float g_src2[NV];
__device__ __align__(16) float g_dst2[NV];
__device__ __align__(16) unsigned g_adjbits[NV * NW];   // 2 MB

// ---------------- f32x2 packed-math helpers --------------------------------
__device__ __forceinline__ unsigned long long pack2(float x, float y) {
    unsigned long long r;
    asm("mov.b64 %0, {%1, %2};" : "=l"(r) : "f"(x), "f"(y));
    return r;
}
__device__ __forceinline__ float2 unpack2(unsigned long long v) {
    float2 r;
    asm("mov.b64 {%0, %1}, %2;" : "=f"(r.x), "=f"(r.y) : "l"(v));
    return r;
}
__device__ __forceinline__ void fma2(unsigned long long& d,
                                     unsigned long long a,
                                     unsigned long long b) {
    asm("fma.rn.f32x2 %0, %1, %2, %0;" : "+l"(d) : "l"(a), "l"(b));
}

// ---------------- K0: adjacency -> bitmask ----------------------------------
__global__ void adjbits_kernel(const int* __restrict__ adj) {
    int idx = blockIdx.x * blockDim.x + threadIdx.x;   // over NV*NV
    unsigned bit = (adj[idx] != 0) ? 1u : 0u;
    unsigned w = __ballot_sync(0xffffffffu, bit);
    if ((threadIdx.x & 31) == 0) g_adjbits[idx >> 5] = w;
}

// ---------------- K1: GEMM  C[4096,256] = A[4096,K] @ B[K,256] --------------
// layer 0: A = x (param), B = W1 + head*K*256, C = g_Wh1 + head*NV*FH, K=512
// layer 1: A = g_h1,      B = W2,              C = g_Wh2,              K=1024
__global__ void __launch_bounds__(256, 2)
gemm_kernel(const float* __restrict__ Aext, const float* __restrict__ B, int layer) {
    __shared__ float Bs[32 * 256];
    __shared__ float As[64][36];

    const int b   = blockIdx.y;
    const int K   = layer ? F2 : F1;
    const float* A = layer ? g_h1 : Aext;
    const float* Bb = B + (size_t)b * K * 256;
    float* C = (layer ? g_Wh2 : g_Wh1 + (size_t)b * NV * FH);

    const int i0  = blockIdx.x * 64;
    const int tid = threadIdx.x;
    const int tr = tid >> 5, tc = tid & 31;
    const int r0 = tr * 8;
    const int cA = tc * 4;         // first 4 output cols
    const int cB = 128 + tc * 4;   // second 4 output cols

    unsigned long long acc[8][4];
#pragma unroll
    for (int u = 0; u < 8; u++)
#pragma unroll
        for (int v = 0; v < 4; v++) acc[u][v] = 0ULL;

    for (int k0 = 0; k0 < K; k0 += 32) {
        // B tile is contiguous 32*256 floats
        const float4* Bp = (const float4*)(Bb + (size_t)k0 * 256);
#pragma unroll
        for (int q = 0; q < 8; q++)
            ((float4*)Bs)[tid + q * 256] = Bp[tid + q * 256];
        // A tile: 64 rows x 32 cols
#pragma unroll
        for (int q = 0; q < 2; q++) {
            int idx = tid + q * 256;          // 0..511
            int row = idx >> 3, c4 = idx & 7;
            float4 v = *(const float4*)(A + (size_t)(i0 + row) * K + k0 + c4 * 4);
            *(float4*)&As[row][c4 * 4] = v;
        }
        __syncthreads();
#pragma unroll
        for (int k = 0; k < 32; k++) {
            ulonglong2 wA = *(const ulonglong2*)(Bs + k * 256 + cA);
            ulonglong2 wB = *(const ulonglong2*)(Bs + k * 256 + cB);
#pragma unroll
            for (int u = 0; u < 8; u++) {
                float p = As[r0 + u][k];
                unsigned long long pp = pack2(p, p);
                fma2(acc[u][0], pp, wA.x);
                fma2(acc[u][1], pp, wA.y);
                fma2(acc[u][2], pp, wB.x);
                fma2(acc[u][3], pp, wB.y);
            }
        }
        __syncthreads();
    }
#pragma unroll
    for (int u = 0; u < 8; u++) {
        float2 f0 = unpack2(acc[u][0]), f1 = unpack2(acc[u][1]);
        float2 f2 = unpack2(acc[u][2]), f3 = unpack2(acc[u][3]);
        float* Cr = C + (size_t)(i0 + r0 + u) * 256;
        *(float4*)(Cr + cA) = make_float4(f0.x, f0.y, f1.x, f1.y);
        *(float4*)(Cr + cB) = make_float4(f2.x, f2.y, f3.x, f3.y);
    }
}

// ---------------- K2: src/dst projections -----------------------------------
__global__ void srcdst_kernel(const float* __restrict__ avec, int layer) {
    __shared__ float sa[2 * FH];
    const int b = blockIdx.y;
    const float* Wh = layer ? g_Wh2 : g_Wh1 + (size_t)b * NV * FH;
    const float* a  = avec + b * 2 * FH;
    float* src = layer ? g_src2 : g_src1 + b * NV;
    float* dst = layer ? g_dst2 : g_dst1 + b * NV;

    const int tid = threadIdx.x;
    for (int i = tid; i < 2 * FH; i += blockDim.x) sa[i] = a[i];
    __syncthreads();

    const int warp = tid >> 5, lane = tid & 31;
    const int row = blockIdx.x * 8 + warp;
    const float* wr = Wh + (size_t)row * FH;
    float s1 = 0.f, s2 = 0.f;
#pragma unroll
    for (int v = lane; v < FH; v += 32) {
        float w = wr[v];
        s1 += w * sa[v];
        s2 += w * sa[FH + v];
    }
#pragma unroll
    for (int o = 16; o; o >>= 1) {
        s1 += __shfl_xor_sync(0xffffffffu, s1, o);
        s2 += __shfl_xor_sync(0xffffffffu, s2, o);
    }
    if (lane == 0) { src[row] = s1; dst[row] = s2; }
}

// ---------------- K3: fused masked-exp attention GEMM -----------------------
// out_i = (sum_j w_ij * Wh_j) / (sum_j w_ij),  w_ij = adj ? exp(lrelu(src_i+dst_j)) : 0
// layer 0: Wh=g_Wh1[head], out=g_h1 (ldc=1024, coloff=head*256), ELU epilogue
// layer 1: Wh=g_Wh2,       out=d_out (ldc=256), plain epilogue
__global__ void __launch_bounds__(256, 2)
attn_kernel(float* __restrict__ outExt, int layer) {
    __shared__ float Ws[32 * 256];   // Wh tile [32 j][256 f]
    __shared__ float Ps[32][64];     // transposed P tile [k][row]
    __shared__ float ssrc[64];
    __shared__ float lpart[64][4];

    const int b = blockIdx.y;
    const float* Wh  = layer ? g_Wh2  : g_Wh1 + (size_t)b * NV * FH;
    const float* src = layer ? g_src2 : g_src1 + b * NV;
    const float* dst = layer ? g_dst2 : g_dst1 + b * NV;
    float* out  = layer ? outExt : g_h1;
    const int ldc    = layer ? FO : F2;
    const int coloff = layer ? 0 : b * FH;

    const int i0  = blockIdx.x * 64;
    const int tid = threadIdx.x;
    const int prow = tid & 63, pg = tid >> 6;     // P-phase mapping
    const int tr = tid >> 5, tc = tid & 31;       // GEMM-phase mapping
    const int r0 = tr * 8;
    const int cA = tc * 4, cB = 128 + tc * 4;

    if (tid < 64) ssrc[tid] = src[i0 + tid];
    lpart[prow][pg] = 0.f;

    unsigned long long acc[8][4];
#pragma unroll
    for (int u = 0; u < 8; u++)
#pragma unroll
        for (int v = 0; v < 4; v++) acc[u][v] = 0ULL;

    const unsigned* adjrow = g_adjbits + (size_t)(i0 + prow) * NW;

    for (int j0 = 0; j0 < NV; j0 += 32) {
        __syncthreads();   // previous inner loop done; Ws/Ps free; init visible
        // Wh tile (contiguous 32*256 floats)
        const float4* Wp = (const float4*)(Wh + (size_t)j0 * FH);
#pragma unroll
        for (int q = 0; q < 8; q++)
            ((float4*)Ws)[tid + q * 256] = Wp[tid + q * 256];
        // P tile: this thread handles row=prow, k = pg*8 .. pg*8+7
        {
            unsigned aw = adjrow[j0 >> 5];
            float si = ssrc[prow];
            float4 d0 = *(const float4*)(dst + j0 + pg * 8);
            float4 d1 = *(const float4*)(dst + j0 + pg * 8 + 4);
            float dv[8] = {d0.x, d0.y, d0.z, d0.w, d1.x, d1.y, d1.z, d1.w};
            float s = 0.f;
#pragma unroll
            for (int u = 0; u < 8; u++) {
                int k = pg * 8 + u;
                float e = si + dv[u];
                e = e > 0.f ? e : 0.2f * e;
                float p = ((aw >> k) & 1u) ? __expf(e) : 0.f;
                Ps[k][prow] = p;
                s += p;
            }
            lpart[prow][pg] += s;
        }
        __syncthreads();
        // inner GEMM: acc[64x256] += P[64x32] @ Ws[32x256]
#pragma unroll
        for (int k = 0; k < 32; k++) {
            float4 pa = *(const float4*)&Ps[k][r0];
            float4 pb = *(const float4*)&Ps[k][r0 + 4];
            float pv[8] = {pa.x, pa.y, pa.z, pa.w, pb.x, pb.y, pb.z, pb.w};
            ulonglong2 wA = *(const ulonglong2*)(Ws + k * 256 + cA);
            ulonglong2 wB = *(const ulonglong2*)(Ws + k * 256 + cB);
#pragma unroll
            for (int u = 0; u < 8; u++) {
                unsigned long long pp = pack2(pv[u], pv[u]);
                fma2(acc[u][0], pp, wA.x);
                fma2(acc[u][1], pp, wA.y);
                fma2(acc[u][2], pp, wB.x);
                fma2(acc[u][3], pp, wB.y);
            }
        }
    }
    // epilogue: divide by row sum, optional ELU, store
#pragma unroll
    for (int u = 0; u < 8; u++) {
        int r = r0 + u;
        float l = lpart[r][0] + lpart[r][1] + lpart[r][2] + lpart[r][3];
        float rl = 1.0f / l;
        float2 f0 = unpack2(acc[u][0]), f1 = unpack2(acc[u][1]);
        float2 f2 = unpack2(acc[u][2]), f3 = unpack2(acc[u][3]);
        float o[8] = {f0.x * rl, f0.y * rl, f1.x * rl, f1.y * rl,
                      f2.x * rl, f2.y * rl, f3.x * rl, f3.y * rl};
        if (layer == 0) {   // ELU
#pragma unroll
            for (int v = 0; v < 8; v++)
                o[v] = o[v] > 0.f ? o[v] : (__expf(o[v]) - 1.0f);
        }
        float* Or = out + (size_t)(i0 + r) * ldc + coloff;
        *(float4*)(Or + cA) = make_float4(o[0], o[1], o[2], o[3]);
        *(float4*)(Or + cB) = make_float4(o[4], o[5], o[6], o[7]);
    }
}

// ---------------- launch -----------------------------------------------------
extern "C" void kernel_launch(void* const* d_in, const int* in_sizes, int n_in,
                              void* d_out, int out_size) {
    (void)in_sizes; (void)n_in; (void)out_size;
    const float* x  = (const float*)d_in[0];
    const int*   adj = (const int*)d_in[1];
    const float* W1 = (const float*)d_in[2];
    const float* a1 = (const float*)d_in[3];
    const float* W2 = (const float*)d_in[4];
    const float* a2 = (const float*)d_in[5];
    float* out = (float*)d_out;

    adjbits_kernel<<<(NV * NV) / 256, 256>>>(adj);
    gemm_kernel<<<dim3(NV / 64, NHEADS), 256>>>(x, W1, 0);
    srcdst_kernel<<<dim3(NV / 8, NHEADS), 256>>>(a1, 0);
    attn_kernel<<<dim3(NV / 64, NHEADS), 256>>>(nullptr, 0);
    gemm_kernel<<<dim3(NV / 64, 1), 256>>>(nullptr, W2, 1);
    srcdst_kernel<<<dim3(NV / 8, 1), 256>>>(a2, 1);
    attn_kernel<<<dim3(NV / 64, 1), 256>>>(out, 1);
}

// round 3
// speedup vs baseline: 1.0193x; 1.0193x over previous
#include <cuda_runtime.h>
#include <cstdint>

#define NV 4096
#define F1 512
#define FH 256
#define NHEADS 4
#define F2 1024   // nhid * nheads
#define FO 256
#define NW (NV/32) // 128 bitmask words per row

// ---------------- scratch (static device memory; no allocations) ------------
__device__ __align__(16) float g_Wh1[NHEADS * NV * FH]; // 16 MB
__device__ __align__(16) float g_h1[NV * F2];           // 16 MB
__device__ __align__(16) float g_Wh2[NV * FO];          // 4 MB
__device__ __align__(16) float g_src1[NHEADS * NV];
__device__ __align__(16) float g_dst1[NHEADS * NV];
__device__ __align__(16) float g_src2[NV];
__device__ __align__(16) float g_dst2[NV];
__device__ __align__(16) unsigned g_adjbits[NV * NW];   // 2 MB

// ---------------- f32x2 packed-math helpers --------------------------------
__device__ __forceinline__ unsigned long long pack2(float x, float y) {
    unsigned long long r;
    asm("mov.b64 %0, {%1, %2};" : "=l"(r) : "f"(x), "f"(y));
    return r;
}
__device__ __forceinline__ float2 unpack2(unsigned long long v) {
    float2 r;
    asm("mov.b64 {%0, %1}, %2;" : "=f"(r.x), "=f"(r.y) : "l"(v));
    return r;
}
__device__ __forceinline__ void fma2(unsigned long long& d,
                                     unsigned long long a,
                                     unsigned long long b) {
    asm("fma.rn.f32x2 %0, %1, %2, %0;" : "+l"(d) : "l"(a), "l"(b));
}

// ---------------- tf32 mma helpers ------------------------------------------
__device__ __forceinline__ float tf32r(float x) {
    uint32_t u;
    asm("cvt.rna.tf32.f32 %0, %1;" : "=r"(u) : "f"(x));
    return __uint_as_float(u);
}
__device__ __forceinline__ void mma_tf32(float* d, const uint32_t* a,
                                         uint32_t b0, uint32_t b1) {
    asm volatile(
        "mma.sync.aligned.m16n8k8.row.col.f32.tf32.tf32.f32 "
        "{%0,%1,%2,%3}, {%4,%5,%6,%7}, {%8,%9}, {%0,%1,%2,%3};"
        : "+f"(d[0]), "+f"(d[1]), "+f"(d[2]), "+f"(d[3])
        : "r"(a[0]), "r"(a[1]), "r"(a[2]), "r"(a[3]), "r"(b0), "r"(b1));
}

// ---------------- K0: adjacency -> bitmask ----------------------------------
__global__ void adjbits_kernel(const int* __restrict__ adj) {
    int idx = blockIdx.x * blockDim.x + threadIdx.x;   // over NV*NV
    unsigned bit = (adj[idx] != 0) ? 1u : 0u;
    unsigned w = __ballot_sync(0xffffffffu, bit);
    if ((threadIdx.x & 31) == 0) g_adjbits[idx >> 5] = w;
}

// ---------------- K1: fp32 GEMM  C[4096,256] = A[4096,K] @ B[K,256] ----------
template <int RPB>
__global__ void __launch_bounds__(256, 2)
gemm_kernel(const float* __restrict__ Aext, const float* __restrict__ B, int layer) {
    __shared__ float Bs[32 * 256];
    __shared__ float As[RPB][36];
    const int MR = RPB / 8;

    const int b   = blockIdx.y;
    const int K   = layer ? F2 : F1;
    const float* A = layer ? g_h1 : Aext;
    const float* Bb = B + (size_t)b * K * 256;
    float* C = layer ? g_Wh2 : g_Wh1 + (size_t)b * NV * FH;

    const int i0  = blockIdx.x * RPB;
    const int tid = threadIdx.x;
    const int tr = tid >> 5, tc = tid & 31;
    const int r0 = tr * MR;
    const int cA = tc * 4;
    const int cB = 128 + tc * 4;

    unsigned long long acc[MR][4];
#pragma unroll
    for (int u = 0; u < MR; u++)
#pragma unroll
        for (int v = 0; v < 4; v++) acc[u][v] = 0ULL;

    for (int k0 = 0; k0 < K; k0 += 32) {
        const float4* Bp = (const float4*)(Bb + (size_t)k0 * 256);
#pragma unroll
        for (int q = 0; q < 8; q++)
            ((float4*)Bs)[tid + q * 256] = Bp[tid + q * 256];
#pragma unroll
        for (int q = 0; q < RPB / 32; q++) {
            int idx = tid + q * 256;
            int row = idx >> 3, c4 = idx & 7;
            float4 v = *(const float4*)(A + (size_t)(i0 + row) * K + k0 + c4 * 4);
            *(float4*)&As[row][c4 * 4] = v;
        }
        __syncthreads();
#pragma unroll
        for (int k = 0; k < 32; k++) {
            ulonglong2 wA = *(const ulonglong2*)(Bs + k * 256 + cA);
            ulonglong2 wB = *(const ulonglong2*)(Bs + k * 256 + cB);
#pragma unroll
            for (int u = 0; u < MR; u++) {
                float p = As[r0 + u][k];
                unsigned long long pp = pack2(p, p);
                fma2(acc[u][0], pp, wA.x);
                fma2(acc[u][1], pp, wA.y);
                fma2(acc[u][2], pp, wB.x);
                fma2(acc[u][3], pp, wB.y);
            }
        }
        __syncthreads();
    }
#pragma unroll
    for (int u = 0; u < MR; u++) {
        float2 f0 = unpack2(acc[u][0]), f1 = unpack2(acc[u][1]);
        float2 f2 = unpack2(acc[u][2]), f3 = unpack2(acc[u][3]);
        float* Cr = C + (size_t)(i0 + r0 + u) * 256;
        *(float4*)(Cr + cA) = make_float4(f0.x, f0.y, f1.x, f1.y);
        *(float4*)(Cr + cB) = make_float4(f2.x, f2.y, f3.x, f3.y);
    }
}

// ---------------- K2: src/dst projections (exact fp32) -----------------------
__global__ void srcdst_kernel(const float* __restrict__ avec, int layer) {
    __shared__ float sa[2 * FH];
    const int b = blockIdx.y;
    const float* Wh = layer ? g_Wh2 : g_Wh1 + (size_t)b * NV * FH;
    const float* a  = avec + b * 2 * FH;
    float* src = layer ? g_src2 : g_src1 + b * NV;
    float* dst = layer ? g_dst2 : g_dst1 + b * NV;

    const int tid = threadIdx.x;
    for (int i = tid; i < 2 * FH; i += blockDim.x) sa[i] = a[i];
    __syncthreads();

    const int warp = tid >> 5, lane = tid & 31;
    const int row = blockIdx.x * 8 + warp;
    const float* wr = Wh + (size_t)row * FH;
    float s1 = 0.f, s2 = 0.f;
#pragma unroll
    for (int v = lane; v < FH; v += 32) {
        float w = wr[v];
        s1 += w * sa[v];
        s2 += w * sa[FH + v];
    }
#pragma unroll
    for (int o = 16; o; o >>= 1) {
        s1 += __shfl_xor_sync(0xffffffffu, s1, o);
        s2 += __shfl_xor_sync(0xffffffffu, s2, o);
    }
    if (lane == 0) { src[row] = s1; dst[row] = s2; }
}

// ---------------- K3: mma.sync tf32 fused masked-exp attention ---------------
// CTA: 128 rows x 128 cols of out. 8 warps (4 row-groups x 2 col-groups),
// warp tile 32x64. K-step = 32 neighbors. B (Wh) split hi/lo tf32 (2 MMAs).
#define PSROW 36
__global__ void __launch_bounds__(256, 2)
attn_mma_kernel(float* __restrict__ outExt, int layer) {
    extern __shared__ char smem[];
    float*  Ps  = (float*)smem;                      // [128][36] tf32 P, [row][k]
    float2* Whl = (float2*)(smem + 128 * PSROW * 4); // [128][36] (hi,lo), [n][k]
    float*  ssrc_s = (float*)(smem + 128 * PSROW * 4 + 128 * PSROW * 8);
    float*  lpart  = ssrc_s + 128;                   // [256]

    const int tid  = threadIdx.x;
    const int wid  = tid >> 5, lane = tid & 31;
    const int wr   = wid >> 1, wc = wid & 1;
    const int b    = blockIdx.z;
    const int cb   = blockIdx.y;        // 0/1: which 128-col half
    const int i0   = blockIdx.x * 128;

    const float* Wh  = layer ? g_Wh2  : g_Wh1 + (size_t)b * NV * FH;
    const float* src = layer ? g_src2 : g_src1 + b * NV;
    const float* dst = layer ? g_dst2 : g_dst1 + b * NV;
    float* out = layer ? outExt : g_h1;
    const int ldc    = layer ? FO : F2;
    const int coloff = (layer ? 0 : b * FH) + cb * 128;

    if (tid < 128) ssrc_s[tid] = src[i0 + tid];
    __syncthreads();

    // P-phase mapping: thread -> (row, 16 k's)
    const int prow = tid >> 1;
    const int ph16 = (tid & 1) * 16;
    const float si = ssrc_s[prow];
    const unsigned* adjrow = g_adjbits + (size_t)(i0 + prow) * NW;
    // Wh-load mapping
    const int jrow = tid >> 3;          // 0..31
    const int fg   = (tid & 7) * 4;     // 0,4,..,28
    float lsum = 0.f;

    float d[2][8][4];
#pragma unroll
    for (int mt = 0; mt < 2; mt++)
#pragma unroll
        for (int nt = 0; nt < 8; nt++)
#pragma unroll
            for (int v = 0; v < 4; v++) d[mt][nt][v] = 0.f;

    const int ar = lane >> 2;           // fragment row within 8
    const int ak = lane & 3;            // fragment k within 4

    for (int kt = 0; kt < 128; kt++) {
        const int j0 = kt * 32;
        // ---- global loads (overlap with previous step's MMA latency) ----
        float pv[16];
        {
            unsigned aw = adjrow[kt] >> ph16;
            const float4* dp = (const float4*)(dst + j0 + ph16);
            float4 d0 = dp[0], d1 = dp[1], d2 = dp[2], d3 = dp[3];
            float dv[16] = {d0.x, d0.y, d0.z, d0.w, d1.x, d1.y, d1.z, d1.w,
                            d2.x, d2.y, d2.z, d2.w, d3.x, d3.y, d3.z, d3.w};
#pragma unroll
            for (int u = 0; u < 16; u++) {
                float e = si + dv[u];
                e = e > 0.f ? e : 0.2f * e;
                float p = ((aw >> u) & 1u) ? __expf(e) : 0.f;
                p = tf32r(p);
                lsum += p;
                pv[u] = p;
            }
        }
        float4 wv[4];
        {
            const float* wp = Wh + (size_t)(j0 + jrow) * FH + cb * 128 + fg;
#pragma unroll
            for (int q = 0; q < 4; q++)
                wv[q] = *(const float4*)(wp + q * 32);
        }
        __syncthreads();   // previous MMA LDS done; tiles free
        // ---- store P tile [row][k] ----
#pragma unroll
        for (int g = 0; g < 4; g++)
            *(float4*)&Ps[prow * PSROW + ph16 + 4 * g] =
                make_float4(pv[4*g], pv[4*g+1], pv[4*g+2], pv[4*g+3]);
        // ---- store Wh tile split hi/lo, [n(f)][k(j)] ----
#pragma unroll
        for (int q = 0; q < 4; q++) {
            float vv[4] = {wv[q].x, wv[q].y, wv[q].z, wv[q].w};
#pragma unroll
            for (int c = 0; c < 4; c++) {
                float hi = tf32r(vv[c]);
                float lo = tf32r(vv[c] - hi);
                Whl[(fg + q * 32 + c) * PSROW + jrow] = make_float2(hi, lo);
            }
        }
        __syncthreads();
        // ---- MMA: 4 k-iters of k8, B split into hi+lo ----
#pragma unroll
        for (int kk = 0; kk < 4; kk++) {
            const int k0 = kk * 8;
            uint32_t a[2][4];
#pragma unroll
            for (int mt = 0; mt < 2; mt++) {
                const int m0 = wr * 32 + mt * 16;
                const float* pr = &Ps[(m0 + ar) * PSROW + k0 + ak];
                a[mt][0] = __float_as_uint(pr[0]);
                a[mt][1] = __float_as_uint(pr[8 * PSROW]);
                a[mt][2] = __float_as_uint(pr[4]);
                a[mt][3] = __float_as_uint(pr[8 * PSROW + 4]);
            }
#pragma unroll
            for (int nt = 0; nt < 8; nt++) {
                const int n = wc * 64 + nt * 8 + ar;
                float2 w0 = Whl[n * PSROW + k0 + ak];
                float2 w1 = Whl[n * PSROW + k0 + ak + 4];
                uint32_t bh0 = __float_as_uint(w0.x), bh1 = __float_as_uint(w1.x);
                uint32_t bl0 = __float_as_uint(w0.y), bl1 = __float_as_uint(w1.y);
                mma_tf32(d[0][nt], a[0], bh0, bh1);
                mma_tf32(d[0][nt], a[0], bl0, bl1);
                mma_tf32(d[1][nt], a[1], bh0, bh1);
                mma_tf32(d[1][nt], a[1], bl0, bl1);
            }
        }
    }
    // ---- epilogue: normalize rows, optional ELU, store ----
    lpart[tid] = lsum;     // lpart[2*row + half]
    __syncthreads();
#pragma unroll
    for (int mt = 0; mt < 2; mt++) {
        const int r0 = wr * 32 + mt * 16 + ar;      // local row of c0/c1
        const int r1 = r0 + 8;                      // local row of c2/c3
        const float rl0 = 1.0f / (lpart[2 * r0] + lpart[2 * r0 + 1]);
        const float rl1 = 1.0f / (lpart[2 * r1] + lpart[2 * r1 + 1]);
#pragma unroll
        for (int nt = 0; nt < 8; nt++) {
            const int c = coloff + wc * 64 + nt * 8 + 2 * ak;
            float o0 = d[mt][nt][0] * rl0, o1 = d[mt][nt][1] * rl0;
            float o2 = d[mt][nt][2] * rl1, o3 = d[mt][nt][3] * rl1;
            if (layer == 0) {
                o0 = o0 > 0.f ? o0 : (__expf(o0) - 1.0f);
                o1 = o1 > 0.f ? o1 : (__expf(o1) - 1.0f);
                o2 = o2 > 0.f ? o2 : (__expf(o2) - 1.0f);
                o3 = o3 > 0.f ? o3 : (__expf(o3) - 1.0f);
            }
            *(float2*)(out + (size_t)(i0 + r0) * ldc + c) = make_float2(o0, o1);
            *(float2*)(out + (size_t)(i0 + r1) * ldc + c) = make_float2(o2, o3);
        }
    }
}

#define ATTN_SMEM (128 * PSROW * 4 + 128 * PSROW * 8 + 128 * 4 + 256 * 4)

// ---------------- launch -----------------------------------------------------
extern "C" void kernel_launch(void* const* d_in, const int* in_sizes, int n_in,
                              void* d_out, int out_size) {
    (void)in_sizes; (void)n_in; (void)out_size;
    const float* x   = (const float*)d_in[0];
    const int*   adj = (const int*)d_in[1];
    const float* W1  = (const float*)d_in[2];
    const float* a1  = (const float*)d_in[3];
    const float* W2  = (const float*)d_in[4];
    const float* a2  = (const float*)d_in[5];
    float* out = (float*)d_out;

    static int inited = 0;
    if (!inited) {
        cudaFuncSetAttribute(attn_mma_kernel,
                             cudaFuncAttributeMaxDynamicSharedMemorySize, ATTN_SMEM);
        inited = 1;
    }

    adjbits_kernel<<<(NV * NV) / 256, 256>>>(adj);
    gemm_kernel<64><<<dim3(NV / 64, NHEADS), 256>>>(x, W1, 0);
    srcdst_kernel<<<dim3(NV / 8, NHEADS), 256>>>(a1, 0);
    attn_mma_kernel<<<dim3(NV / 128, 2, NHEADS), 256, ATTN_SMEM>>>(nullptr, 0);
    gemm_kernel<32><<<dim3(NV / 32, 1), 256>>>(nullptr, W2, 1);
    srcdst_kernel<<<dim3(NV / 8, 1), 256>>>(a2, 1);
    attn_mma_kernel<<<dim3(NV / 128, 2, 1), 256, ATTN_SMEM>>>(out, 1);
}

// round 4
// speedup vs baseline: 2.1371x; 2.0966x over previous
#include <cuda_runtime.h>
#include <cstdint>

#define NV 4096
#define F1 512
#define FH 256
#define NHEADS 4
#define F2 1024   // nhid * nheads
#define FO 256
#define NW (NV/32) // 128 bitmask words per row

#define PSROW 36   // P tile row stride (floats): conflict-free A frags
#define WROW  264  // Wh tile row stride (floats): 264%32==8 -> conflict-free B frags

// ---------------- scratch (static device memory; no allocations) ------------
__device__ __align__(16) float g_Wh1[NHEADS * NV * FH]; // 16 MB
__device__ __align__(16) float g_h1[NV * F2];           // 16 MB
__device__ __align__(16) float g_Wh2[NV * FO];          // 4 MB
__device__ __align__(16) float g_src1[NHEADS * NV];
__device__ __align__(16) float g_dst1[NHEADS * NV];
__device__ __align__(16) float g_src2[NV];
__device__ __align__(16) float g_dst2[NV];
__device__ __align__(16) unsigned g_adjbits[NV * NW];   // 2 MB

// ---------------- f32x2 packed-math helpers (scalar GEMM2) ------------------
__device__ __forceinline__ unsigned long long pack2(float x, float y) {
    unsigned long long r;
    asm("mov.b64 %0, {%1, %2};" : "=l"(r) : "f"(x), "f"(y));
    return r;
}
__device__ __forceinline__ float2 unpack2(unsigned long long v) {
    float2 r;
    asm("mov.b64 {%0, %1}, %2;" : "=f"(r.x), "=f"(r.y) : "l"(v));
    return r;
}
__device__ __forceinline__ void fma2(unsigned long long& d,
                                     unsigned long long a,
                                     unsigned long long b) {
    asm("fma.rn.f32x2 %0, %1, %2, %0;" : "+l"(d) : "l"(a), "l"(b));
}

// ---------------- tf32 mma helpers ------------------------------------------
__device__ __forceinline__ float tf32r(float x) {
    uint32_t u;
    asm("cvt.rna.tf32.f32 %0, %1;" : "=r"(u) : "f"(x));
    return __uint_as_float(u);
}
__device__ __forceinline__ void mma_tf32(float* d, const uint32_t* a,
                                         uint32_t b0, uint32_t b1) {
    asm volatile(
        "mma.sync.aligned.m16n8k8.row.col.f32.tf32.tf32.f32 "
        "{%0,%1,%2,%3}, {%4,%5,%6,%7}, {%8,%9}, {%0,%1,%2,%3};"
        : "+f"(d[0]), "+f"(d[1]), "+f"(d[2]), "+f"(d[3])
        : "r"(a[0]), "r"(a[1]), "r"(a[2]), "r"(a[3]), "r"(b0), "r"(b1));
}

// ---------------- K0: adjacency -> bitmask ----------------------------------
__global__ void adjbits_kernel(const int* __restrict__ adj) {
    int idx = blockIdx.x * blockDim.x + threadIdx.x;   // over NV*NV
    unsigned bit = (adj[idx] != 0) ? 1u : 0u;
    unsigned w = __ballot_sync(0xffffffffu, bit);
    if ((threadIdx.x & 31) == 0) g_adjbits[idx >> 5] = w;
}

// ---------------- K1: mma tf32 GEMM1  Wh1[h] = x @ W1[h]  --------------------
// Tile 128x256, K=512 (16 k-steps of 32), 512 threads, 16 warps (4x4).
__device__ __forceinline__ void g1_fill(
    float* Ab, float* Bb, int kt,
    const float* __restrict__ x, const float* __restrict__ W1b,
    int i0, int arow, int akb, int jrow, int fbase) {
    const int k0 = kt * 32;
    // B tile: W1b[k0+jrow][fbase + 64q] -> Bb[jrow*WROW + f]
    const float* wp = W1b + (size_t)(k0 + jrow) * FH + fbase;
    float4 wv[4];
#pragma unroll
    for (int q = 0; q < 4; q++) wv[q] = *(const float4*)(wp + 64 * q);
    // A tile: x[i0+arow][k0+akb .. +7] -> Ab[arow*PSROW + akb]
    const float* ap = x + (size_t)(i0 + arow) * F1 + k0 + akb;
    float4 a0 = *(const float4*)(ap);
    float4 a1 = *(const float4*)(ap + 4);
    float* abp = Ab + arow * PSROW + akb;
    *(float4*)abp = make_float4(tf32r(a0.x), tf32r(a0.y), tf32r(a0.z), tf32r(a0.w));
    *(float4*)(abp + 4) = make_float4(tf32r(a1.x), tf32r(a1.y), tf32r(a1.z), tf32r(a1.w));
#pragma unroll
    for (int q = 0; q < 4; q++)
        *(float4*)(Bb + jrow * WROW + fbase + 64 * q) =
            make_float4(tf32r(wv[q].x), tf32r(wv[q].y), tf32r(wv[q].z), tf32r(wv[q].w));
}

#define G1_SMEM (2 * 128 * PSROW * 4 + 2 * 32 * WROW * 4)

__global__ void __launch_bounds__(512, 1)
gemm1_mma_kernel(const float* __restrict__ x, const float* __restrict__ W1) {
    extern __shared__ char smem[];
    float* Ps  = (float*)smem;                           // [2][128*PSROW]
    float* Whs = (float*)(smem + 2 * 128 * PSROW * 4);   // [2][32*WROW]

    const int tid = threadIdx.x;
    const int wid = tid >> 5, lane = tid & 31;
    const int wr = wid >> 2, wc = wid & 3;
    const int b  = blockIdx.y;
    const int i0 = blockIdx.x * 128;
    const float* W1b = W1 + (size_t)b * F1 * FH;
    float* C = g_Wh1 + (size_t)b * NV * FH;

    const int arow = tid >> 2, akb = (tid & 3) * 8;
    const int jrow = tid >> 4, fbase = (tid & 15) * 4;
    const int ar = lane >> 2, ak = lane & 3;

    float d[2][8][4];
#pragma unroll
    for (int mt = 0; mt < 2; mt++)
#pragma unroll
        for (int nt = 0; nt < 8; nt++)
#pragma unroll
            for (int v = 0; v < 4; v++) d[mt][nt][v] = 0.f;

    g1_fill(Ps, Whs, 0, x, W1b, i0, arow, akb, jrow, fbase);
    __syncthreads();

    const int NKT = F1 / 32;   // 16
    for (int kt = 0; kt < NKT; kt++) {
        const int bb = kt & 1;
        if (kt + 1 < NKT)
            g1_fill(Ps + (bb ^ 1) * 128 * PSROW, Whs + (bb ^ 1) * 32 * WROW,
                    kt + 1, x, W1b, i0, arow, akb, jrow, fbase);
        const float* pB = Ps + bb * 128 * PSROW;
        const float* wB = Whs + bb * 32 * WROW;
#pragma unroll
        for (int kk = 0; kk < 4; kk++) {
            const int k0 = kk * 8;
            uint32_t a[2][4];
#pragma unroll
            for (int mt = 0; mt < 2; mt++) {
                const float* pr = pB + (wr * 32 + mt * 16 + ar) * PSROW + k0 + ak;
                a[mt][0] = __float_as_uint(pr[0]);
                a[mt][1] = __float_as_uint(pr[8 * PSROW]);
                a[mt][2] = __float_as_uint(pr[4]);
                a[mt][3] = __float_as_uint(pr[8 * PSROW + 4]);
            }
#pragma unroll
            for (int nt = 0; nt < 8; nt++) {
                const int n = wc * 64 + nt * 8 + ar;
                uint32_t b0 = __float_as_uint(wB[(k0 + ak) * WROW + n]);
                uint32_t b1 = __float_as_uint(wB[(k0 + ak + 4) * WROW + n]);
                mma_tf32(d[0][nt], a[0], b0, b1);
                mma_tf32(d[1][nt], a[1], b0, b1);
            }
        }
        __syncthreads();
    }
#pragma unroll
    for (int mt = 0; mt < 2; mt++) {
        const int r0 = wr * 32 + mt * 16 + ar;
        const int r1 = r0 + 8;
#pragma unroll
        for (int nt = 0; nt < 8; nt++) {
            const int c = wc * 64 + nt * 8 + 2 * ak;
            *(float2*)(C + (size_t)(i0 + r0) * FH + c) = make_float2(d[mt][nt][0], d[mt][nt][1]);
            *(float2*)(C + (size_t)(i0 + r1) * FH + c) = make_float2(d[mt][nt][2], d[mt][nt][3]);
        }
    }
}

// ---------------- K1b: scalar fp32 GEMM2 (exact h1 @ W2) ---------------------
template <int RPB>
__global__ void __launch_bounds__(256, 2)
gemm_kernel(const float* __restrict__ B) {
    __shared__ float Bs[32 * 256];
    __shared__ float As[RPB][36];
    const int MR = RPB / 8;
    const int K = F2;
    const float* A = g_h1;
    float* C = g_Wh2;

    const int i0  = blockIdx.x * RPB;
    const int tid = threadIdx.x;
    const int tr = tid >> 5, tc = tid & 31;
    const int r0 = tr * MR;
    const int cA = tc * 4;
    const int cB = 128 + tc * 4;

    unsigned long long acc[MR][4];
#pragma unroll
    for (int u = 0; u < MR; u++)
#pragma unroll
        for (int v = 0; v < 4; v++) acc[u][v] = 0ULL;

    for (int k0 = 0; k0 < K; k0 += 32) {
        const float4* Bp = (const float4*)(B + (size_t)k0 * 256);
#pragma unroll
        for (int q = 0; q < 8; q++)
            ((float4*)Bs)[tid + q * 256] = Bp[tid + q * 256];
#pragma unroll
        for (int q = 0; q < RPB / 32; q++) {
            int idx = tid + q * 256;
            int row = idx >> 3, c4 = idx & 7;
            float4 v = *(const float4*)(A + (size_t)(i0 + row) * K + k0 + c4 * 4);
            *(float4*)&As[row][c4 * 4] = v;
        }
        __syncthreads();
#pragma unroll
        for (int k = 0; k < 32; k++) {
            ulonglong2 wA = *(const ulonglong2*)(Bs + k * 256 + cA);
            ulonglong2 wB = *(const ulonglong2*)(Bs + k * 256 + cB);
#pragma unroll
            for (int u = 0; u < MR; u++) {
                float p = As[r0 + u][k];
                unsigned long long pp = pack2(p, p);
                fma2(acc[u][0], pp, wA.x);
                fma2(acc[u][1], pp, wA.y);
                fma2(acc[u][2], pp, wB.x);
                fma2(acc[u][3], pp, wB.y);
            }
        }
        __syncthreads();
    }
#pragma unroll
    for (int u = 0; u < MR; u++) {
        float2 f0 = unpack2(acc[u][0]), f1 = unpack2(acc[u][1]);
        float2 f2 = unpack2(acc[u][2]), f3 = unpack2(acc[u][3]);
        float* Cr = C + (size_t)(i0 + r0 + u) * 256;
        *(float4*)(Cr + cA) = make_float4(f0.x, f0.y, f1.x, f1.y);
        *(float4*)(Cr + cB) = make_float4(f2.x, f2.y, f3.x, f3.y);
    }
}

// ---------------- K2: src/dst projections (exact fp32) -----------------------
__global__ void srcdst_kernel(const float* __restrict__ avec, int layer) {
    __shared__ float sa[2 * FH];
    const int b = blockIdx.y;
    const float* Wh = layer ? g_Wh2 : g_Wh1 + (size_t)b * NV * FH;
    const float* a  = avec + b * 2 * FH;
    float* src = layer ? g_src2 : g_src1 + b * NV;
    float* dst = layer ? g_dst2 : g_dst1 + b * NV;

    const int tid = threadIdx.x;
    for (int i = tid; i < 2 * FH; i += blockDim.x) sa[i] = a[i];
    __syncthreads();

    const int warp = tid >> 5, lane = tid & 31;
    const int row = blockIdx.x * 8 + warp;
    const float* wr = Wh + (size_t)row * FH;
    float s1 = 0.f, s2 = 0.f;
#pragma unroll
    for (int v = lane; v < FH; v += 32) {
        float w = wr[v];
        s1 += w * sa[v];
        s2 += w * sa[FH + v];
    }
#pragma unroll
    for (int o = 16; o; o >>= 1) {
        s1 += __shfl_xor_sync(0xffffffffu, s1, o);
        s2 += __shfl_xor_sync(0xffffffffu, s2, o);
    }
    if (lane == 0) { src[row] = s1; dst[row] = s2; }
}

// ---------------- K3: mma tf32 fused masked-exp attention --------------------
// CTA: ROWS x 256 out. 512 threads, 16 warps (4 row-groups x 4 col-groups),
// warp tile (ROWS/4) x 64. K-step 32. Single tf32, double-buffered SMEM.
template <int ROWS>
__device__ __forceinline__ float attn_fill(
    float* Pb, float* Wb, int kt,
    const float* __restrict__ Wh, const float* __restrict__ dst,
    const unsigned* __restrict__ adjrow, float si,
    int prow, int kbase, int jrow, int fbase) {
    constexpr int PG  = 512 / ROWS;
    constexpr int KPT = 32 / PG;
    const int j0 = kt * 32;
    // Wh tile loads first (LDG latency hidden under exp + MMA)
    const float* wp = Wh + (size_t)(j0 + jrow) * FH + fbase;
    float4 wv[4];
#pragma unroll
    for (int q = 0; q < 4; q++) wv[q] = *(const float4*)(wp + 64 * q);
    // P values
    unsigned aw = adjrow[kt] >> kbase;
    float lsum = 0.f;
    float pv[KPT];
#pragma unroll
    for (int g = 0; g < KPT / 4; g++) {
        float4 dv = *(const float4*)(dst + j0 + kbase + 4 * g);
        float dd[4] = {dv.x, dv.y, dv.z, dv.w};
#pragma unroll
        for (int c = 0; c < 4; c++) {
            const int u = 4 * g + c;
            float e = si + dd[c];
            e = e > 0.f ? e : 0.2f * e;
            float p = ((aw >> u) & 1u) ? __expf(e) : 0.f;
            p = tf32r(p);
            lsum += p;
            pv[u] = p;
        }
    }
    float* pb = Pb + prow * PSROW + kbase;
#pragma unroll
    for (int g = 0; g < KPT / 4; g++)
        *(float4*)(pb + 4 * g) =
            make_float4(pv[4*g], pv[4*g+1], pv[4*g+2], pv[4*g+3]);
#pragma unroll
    for (int q = 0; q < 4; q++)
        *(float4*)(Wb + jrow * WROW + fbase + 64 * q) =
            make_float4(tf32r(wv[q].x), tf32r(wv[q].y), tf32r(wv[q].z), tf32r(wv[q].w));
    return lsum;
}

#define ATTN_SMEM(R) (2 * (R) * PSROW * 4 + 2 * 32 * WROW * 4 + (R) * 4 + 512 * 4)

template <int ROWS>
__global__ void __launch_bounds__(512, 1)
attn_mma_kernel(float* __restrict__ outExt, int layer) {
    constexpr int MT = ROWS / 64;       // m16 tiles per row-group
    constexpr int PG = 512 / ROWS;
    extern __shared__ char smem[];
    float* Ps  = (float*)smem;                              // [2][ROWS*PSROW]
    float* Whs = (float*)(smem + 2 * ROWS * PSROW * 4);     // [2][32*WROW]
    float* ssrc_s = (float*)(smem + 2 * ROWS * PSROW * 4 + 2 * 32 * WROW * 4);
    float* lpart  = ssrc_s + ROWS;                          // [512]

    const int tid = threadIdx.x;
    const int wid = tid >> 5, lane = tid & 31;
    const int wr = wid >> 2, wc = wid & 3;
    const int b  = blockIdx.z;
    const int i0 = blockIdx.x * ROWS;

    const float* Wh  = layer ? g_Wh2  : g_Wh1 + (size_t)b * NV * FH;
    const float* src = layer ? g_src2 : g_src1 + b * NV;
    const float* dst = layer ? g_dst2 : g_dst1 + b * NV;
    float* out = layer ? outExt : g_h1;
    const int ldc    = layer ? FO : F2;
    const int coloff = layer ? 0 : b * FH;

    if (tid < ROWS) ssrc_s[tid] = src[i0 + tid];
    __syncthreads();

    const int prow  = tid / PG;
    const int kbase = (tid % PG) * (32 / PG);
    const float si  = ssrc_s[prow];
    const unsigned* adjrow = g_adjbits + (size_t)(i0 + prow) * NW;
    const int jrow = tid >> 4, fbase = (tid & 15) * 4;
    const int ar = lane >> 2, ak = lane & 3;

    float d[MT][8][4];
#pragma unroll
    for (int mt = 0; mt < MT; mt++)
#pragma unroll
        for (int nt = 0; nt < 8; nt++)
#pragma unroll
            for (int v = 0; v < 4; v++) d[mt][nt][v] = 0.f;

    float lsum = attn_fill<ROWS>(Ps, Whs, 0, Wh, dst, adjrow, si,
                                 prow, kbase, jrow, fbase);
    __syncthreads();

    const int NKT = NV / 32;   // 128
    for (int kt = 0; kt < NKT; kt++) {
        const int bb = kt & 1;
        if (kt + 1 < NKT)
            lsum += attn_fill<ROWS>(Ps + (bb ^ 1) * ROWS * PSROW,
                                    Whs + (bb ^ 1) * 32 * WROW,
                                    kt + 1, Wh, dst, adjrow, si,
                                    prow, kbase, jrow, fbase);
        const float* pB = Ps + bb * ROWS * PSROW;
        const float* wB = Whs + bb * 32 * WROW;
#pragma unroll
        for (int kk = 0; kk < 4; kk++) {
            const int k0 = kk * 8;
            uint32_t a[MT][4];
#pragma unroll
            for (int mt = 0; mt < MT; mt++) {
                const float* pr = pB + (wr * 16 * MT + mt * 16 + ar) * PSROW + k0 + ak;
                a[mt][0] = __float_as_uint(pr[0]);
                a[mt][1] = __float_as_uint(pr[8 * PSROW]);
                a[mt][2] = __float_as_uint(pr[4]);
                a[mt][3] = __float_as_uint(pr[8 * PSROW + 4]);
            }
#pragma unroll
            for (int nt = 0; nt < 8; nt++) {
                const int n = wc * 64 + nt * 8 + ar;
                uint32_t b0 = __float_as_uint(wB[(k0 + ak) * WROW + n]);
                uint32_t b1 = __float_as_uint(wB[(k0 + ak + 4) * WROW + n]);
#pragma unroll
                for (int mt = 0; mt < MT; mt++)
                    mma_tf32(d[mt][nt], a[mt], b0, b1);
            }
        }
        __syncthreads();
    }
    lpart[tid] = lsum;
    __syncthreads();

#pragma unroll
    for (int mt = 0; mt < MT; mt++) {
        const int r0 = wr * 16 * MT + mt * 16 + ar;
        const int r1 = r0 + 8;
        float l0 = 0.f, l1 = 0.f;
#pragma unroll
        for (int g = 0; g < PG; g++) {
            l0 += lpart[r0 * PG + g];
            l1 += lpart[r1 * PG + g];
        }
        const float rl0 = 1.0f / l0;
        const float rl1 = 1.0f / l1;
#pragma unroll
        for (int nt = 0; nt < 8; nt++) {
            const int c = coloff + wc * 64 + nt * 8 + 2 * ak;
            float o0 = d[mt][nt][0] * rl0, o1 = d[mt][nt][1] * rl0;
            float o2 = d[mt][nt][2] * rl1, o3 = d[mt][nt][3] * rl1;
            if (layer == 0) {
                o0 = o0 > 0.f ? o0 : (__expf(o0) - 1.0f);
                o1 = o1 > 0.f ? o1 : (__expf(o1) - 1.0f);
                o2 = o2 > 0.f ? o2 : (__expf(o2) - 1.0f);
                o3 = o3 > 0.f ? o3 : (__expf(o3) - 1.0f);
            }
            *(float2*)(out + (size_t)(i0 + r0) * ldc + c) = make_float2(o0, o1);
            *(float2*)(out + (size_t)(i0 + r1) * ldc + c) = make_float2(o2, o3);
        }
    }
}

// ---------------- launch -----------------------------------------------------
extern "C" void kernel_launch(void* const* d_in, const int* in_sizes, int n_in,
                              void* d_out, int out_size) {
    (void)in_sizes; (void)n_in; (void)out_size;
    const float* x   = (const float*)d_in[0];
    const int*   adj = (const int*)d_in[1];
    const float* W1  = (const float*)d_in[2];
    const float* a1  = (const float*)d_in[3];
    const float* W2  = (const float*)d_in[4];
    const float* a2  = (const float*)d_in[5];
    float* out = (float*)d_out;

    static int inited = 0;
    if (!inited) {
        cudaFuncSetAttribute(attn_mma_kernel<128>,
                             cudaFuncAttributeMaxDynamicSharedMemorySize, ATTN_SMEM(128));
        cudaFuncSetAttribute(attn_mma_kernel<64>,
                             cudaFuncAttributeMaxDynamicSharedMemorySize, ATTN_SMEM(64));
        cudaFuncSetAttribute(gemm1_mma_kernel,
                             cudaFuncAttributeMaxDynamicSharedMemorySize, G1_SMEM);
        inited = 1;
    }

    adjbits_kernel<<<(NV * NV) / 256, 256>>>(adj);
    gemm1_mma_kernel<<<dim3(NV / 128, NHEADS), 512, G1_SMEM>>>(x, W1);
    srcdst_kernel<<<dim3(NV / 8, NHEADS), 256>>>(a1, 0);
    attn_mma_kernel<128><<<dim3(NV / 128, 1, NHEADS), 512, ATTN_SMEM(128)>>>(nullptr, 0);
    gemm_kernel<32><<<dim3(NV / 32, 1), 256>>>(W2);
    srcdst_kernel<<<dim3(NV / 8, 1), 256>>>(a2, 1);
    attn_mma_kernel<64><<<dim3(NV / 64, 1, 1), 512, ATTN_SMEM(64)>>>(out, 1);
}

// round 5
// speedup vs baseline: 2.3499x; 1.0996x over previous
#include <cuda_runtime.h>
#include <cstdint>

#define NV 4096
#define F1 512
#define FH 256
#define NHEADS 4
#define F2 1024   // nhid * nheads
#define FO 256
#define NW (NV/32) // 128 bitmask words per row

#define PSROW 36   // P tile row stride (floats): conflict-free A frags
#define WROW  264  // Wh tile row stride (floats): 264%32==8 -> conflict-free B frags

// ---------------- scratch (static device memory; no allocations) ------------
__device__ __align__(16) float  g_Wh1[NHEADS * NV * FH]; // 16 MB
__device__ __align__(16) float  g_h1[NV * F2];           // 16 MB
__device__ __align__(16) float  g_Wh2[NV * FO];          // 4 MB
__device__ __align__(16) float4 g_sT1[NHEADS * NV];      // (s, e^s, e^.2s, _)
__device__ __align__(16) float  g_dst1[NHEADS * NV];     // raw d
__device__ __align__(16) float2 g_ed1[NHEADS * NV];      // (e^d, e^.2d)
__device__ __align__(16) float4 g_sT2[NV];
__device__ __align__(16) float  g_dst2[NV];
__device__ __align__(16) float2 g_ed2[NV];
__device__ __align__(16) float  g_np[2 * NV * FO];       // L1 split numerators
__device__ __align__(16) float  g_lp[2 * NV];            // L1 split denominators
__device__ __align__(16) unsigned g_adjbits[NV * NW];    // 2 MB

// ---------------- tf32 mma helpers ------------------------------------------
__device__ __forceinline__ float tf32r(float x) {
    uint32_t u;
    asm("cvt.rna.tf32.f32 %0, %1;" : "=r"(u) : "f"(x));
    return __uint_as_float(u);
}
__device__ __forceinline__ void mma_tf32(float* d, const uint32_t* a,
                                         uint32_t b0, uint32_t b1) {
    asm volatile(
        "mma.sync.aligned.m16n8k8.row.col.f32.tf32.tf32.f32 "
        "{%0,%1,%2,%3}, {%4,%5,%6,%7}, {%8,%9}, {%0,%1,%2,%3};"
        : "+f"(d[0]), "+f"(d[1]), "+f"(d[2]), "+f"(d[3])
        : "r"(a[0]), "r"(a[1]), "r"(a[2]), "r"(a[3]), "r"(b0), "r"(b1));
}

// ---------------- K0: adjacency -> bitmask ----------------------------------
__global__ void adjbits_kernel(const int* __restrict__ adj) {
    int idx = blockIdx.x * blockDim.x + threadIdx.x;   // over NV*NV
    unsigned bit = (adj[idx] != 0) ? 1u : 0u;
    unsigned w = __ballot_sync(0xffffffffu, bit);
    if ((threadIdx.x & 31) == 0) g_adjbits[idx >> 5] = w;
}

// ---------------- K1: tf32 mma GEMM  C[*,256] = A[*,K] @ B[K,256] ------------
// 512 threads, 16 warps (4x4). Warp tile (ROWS/4) x 64.
template <int ROWS>
__global__ void __launch_bounds__(512, 1)
gemm_tf32_kernel(const float* __restrict__ A, const float* __restrict__ B,
                 float* __restrict__ C, int K, long bStride, long cStride) {
    constexpr int MT = ROWS / 64;
    constexpr int TPR = 512 / ROWS;     // threads per A-row
    constexpr int AK  = 32 / TPR;       // A cols per thread
    extern __shared__ char smem[];
    float* As = (float*)smem;                            // [2][ROWS*PSROW]
    float* Bs = (float*)(smem + 2 * ROWS * PSROW * 4);   // [2][32*WROW]

    const int tid = threadIdx.x;
    const int wid = tid >> 5, lane = tid & 31;
    const int wr = wid >> 2, wc = wid & 3;
    const float* Bb = B + (size_t)blockIdx.y * bStride;
    float* Cb = C + (size_t)blockIdx.y * cStride;
    const int i0 = blockIdx.x * ROWS;

    const int arow = tid / TPR, ak0 = (tid % TPR) * AK;
    const int jrow = tid >> 4, fbase = (tid & 15) * 4;
    const int ar = lane >> 2, ak = lane & 3;

    float d[MT][8][4];
#pragma unroll
    for (int mt = 0; mt < MT; mt++)
#pragma unroll
        for (int nt = 0; nt < 8; nt++)
#pragma unroll
            for (int v = 0; v < 4; v++) d[mt][nt][v] = 0.f;

    const int NKT = K / 32;
    for (int kt = 0; kt < NKT; kt++) {
        const int bb = kt & 1;
        const int k0g = kt * 32;
        // fill buffer bb
        {
            const float* wp = Bb + (size_t)(k0g + jrow) * FH + fbase;
            float* bs = Bs + bb * 32 * WROW + jrow * WROW + fbase;
#pragma unroll
            for (int q = 0; q < 4; q++) {
                float4 v = *(const float4*)(wp + 64 * q);
                *(float4*)(bs + 64 * q) =
                    make_float4(tf32r(v.x), tf32r(v.y), tf32r(v.z), tf32r(v.w));
            }
            const float* ap = A + (size_t)(i0 + arow) * K + k0g + ak0;
            float* as = As + bb * ROWS * PSROW + arow * PSROW + ak0;
#pragma unroll
            for (int q = 0; q < AK / 4; q++) {
                float4 v = *(const float4*)(ap + 4 * q);
                *(float4*)(as + 4 * q) =
                    make_float4(tf32r(v.x), tf32r(v.y), tf32r(v.z), tf32r(v.w));
            }
        }
        __syncthreads();
        const float* pB = As + bb * ROWS * PSROW;
        const float* wB = Bs + bb * 32 * WROW;
#pragma unroll
        for (int kk = 0; kk < 4; kk++) {
            const int k0 = kk * 8;
            uint32_t a[MT][4];
#pragma unroll
            for (int mt = 0; mt < MT; mt++) {
                const float* pr = pB + (wr * 16 * MT + mt * 16 + ar) * PSROW + k0 + ak;
                a[mt][0] = __float_as_uint(pr[0]);
                a[mt][1] = __float_as_uint(pr[8 * PSROW]);
                a[mt][2] = __float_as_uint(pr[4]);
                a[mt][3] = __float_as_uint(pr[8 * PSROW + 4]);
            }
#pragma unroll
            for (int nt = 0; nt < 8; nt++) {
                const int n = wc * 64 + nt * 8 + ar;
                uint32_t b0 = __float_as_uint(wB[(k0 + ak) * WROW + n]);
                uint32_t b1 = __float_as_uint(wB[(k0 + ak + 4) * WROW + n]);
#pragma unroll
                for (int mt = 0; mt < MT; mt++)
                    mma_tf32(d[mt][nt], a[mt], b0, b1);
            }
        }
        __syncthreads();
    }
#pragma unroll
    for (int mt = 0; mt < MT; mt++) {
        const int r0 = wr * 16 * MT + mt * 16 + ar;
        const int r1 = r0 + 8;
#pragma unroll
        for (int nt = 0; nt < 8; nt++) {
            const int c = wc * 64 + nt * 8 + 2 * ak;
            *(float2*)(Cb + (size_t)(i0 + r0) * FH + c) = make_float2(d[mt][nt][0], d[mt][nt][1]);
            *(float2*)(Cb + (size_t)(i0 + r1) * FH + c) = make_float2(d[mt][nt][2], d[mt][nt][3]);
        }
    }
}

#define GEMM_SMEM(R) (2 * (R) * PSROW * 4 + 2 * 32 * WROW * 4)

// ---------------- K2: src/dst projections + exp tables -----------------------
__global__ void srcdst_kernel(const float* __restrict__ avec, int layer) {
    __shared__ float sa[2 * FH];
    const int b = blockIdx.y;
    const float* Wh = layer ? g_Wh2 : g_Wh1 + (size_t)b * NV * FH;
    const float* a  = avec + b * 2 * FH;
    float4* sT = layer ? g_sT2  : g_sT1  + b * NV;
    float*  dR = layer ? g_dst2 : g_dst1 + b * NV;
    float2* ed = layer ? g_ed2  : g_ed1  + b * NV;

    const int tid = threadIdx.x;
    for (int i = tid; i < 2 * FH; i += blockDim.x) sa[i] = a[i];
    __syncthreads();

    const int warp = tid >> 5, lane = tid & 31;
    const int row = blockIdx.x * 8 + warp;
    const float* wr = Wh + (size_t)row * FH;
    float s1 = 0.f, s2 = 0.f;
#pragma unroll
    for (int v = lane; v < FH; v += 32) {
        float w = wr[v];
        s1 += w * sa[v];
        s2 += w * sa[FH + v];
    }
#pragma unroll
    for (int o = 16; o; o >>= 1) {
        s1 += __shfl_xor_sync(0xffffffffu, s1, o);
        s2 += __shfl_xor_sync(0xffffffffu, s2, o);
    }
    if (lane == 0) {
        sT[row] = make_float4(s1, __expf(s1), __expf(0.2f * s1), 0.f);
        dR[row] = s2;
        ed[row] = make_float2(__expf(s2), __expf(0.2f * s2));
    }
}

// ---------------- K3: tf32 mma fused attention (no inner-loop exp) -----------
// w_ij = adj ? (e>0 ? e^s_i * e^d_j : e^.2s_i * e^.2d_j) : 0, e = s_i + d_j.
// Pipelined: LDG(kt+1) -> MMA(kt) -> compute/STS(kt+1) -> sync.
template <int ROWS, int PARTIAL>
__global__ void __launch_bounds__(512, 1)
attn_kernel(float* __restrict__ outExt) {
    constexpr int MT  = ROWS / 64;
    constexpr int PG  = 512 / ROWS;
    constexpr int KPT = 32 / PG;
    extern __shared__ char smem[];
    float* Ps    = (float*)smem;                           // [2][ROWS*PSROW]
    float* Whs   = (float*)(smem + 2 * ROWS * PSROW * 4);  // [2][32*WROW]
    float* lpart = (float*)(smem + 2 * ROWS * PSROW * 4 + 2 * 32 * WROW * 4);

    const int tid = threadIdx.x;
    const int wid = tid >> 5, lane = tid & 31;
    const int wr = wid >> 2, wc = wid & 3;
    const int i0 = blockIdx.x * ROWS;

    const float* Wh; const float4* sT; const float* dR; const float2* edT;
    int jbase, NKT;
    if (PARTIAL) {
        Wh = g_Wh2; sT = g_sT2; dR = g_dst2; edT = g_ed2;
        jbase = blockIdx.y * (NV / 2); NKT = (NV / 2) / 32;
    } else {
        const int b = blockIdx.z;
        Wh = g_Wh1 + (size_t)b * NV * FH;
        sT = g_sT1 + b * NV; dR = g_dst1 + b * NV; edT = g_ed1 + b * NV;
        jbase = 0; NKT = NV / 32;
    }

    const int prow = tid / PG;
    const int kbase = (tid % PG) * KPT;
    const float4 sv = sT[i0 + prow];          // (s, e^s, e^.2s, _)
    const unsigned* adjrow = g_adjbits + (size_t)(i0 + prow) * NW + (jbase >> 5);
    const int jrow = tid >> 4, fbase = (tid & 15) * 4;
    const int ar = lane >> 2, ak = lane & 3;

    float d[MT][8][4];
#pragma unroll
    for (int mt = 0; mt < MT; mt++)
#pragma unroll
        for (int nt = 0; nt < 8; nt++)
#pragma unroll
            for (int v = 0; v < 4; v++) d[mt][nt][v] = 0.f;
    float lsum = 0.f;

    // ---- prologue: fill buffer 0 (kt = 0) ----
    {
        const int j0 = jbase;
        const float* wp = Wh + (size_t)(j0 + jrow) * FH + fbase;
        float* bs = Whs + jrow * WROW + fbase;
#pragma unroll
        for (int q = 0; q < 4; q++) {
            float4 v = *(const float4*)(wp + 64 * q);
            *(float4*)(bs + 64 * q) =
                make_float4(tf32r(v.x), tf32r(v.y), tf32r(v.z), tf32r(v.w));
        }
        unsigned aw = adjrow[0] >> kbase;
        float dv[KPT]; float2 ev[KPT];
#pragma unroll
        for (int g = 0; g < KPT / 4; g++) {
            float4 t = *(const float4*)(dR + j0 + kbase + 4 * g);
            dv[4*g] = t.x; dv[4*g+1] = t.y; dv[4*g+2] = t.z; dv[4*g+3] = t.w;
        }
#pragma unroll
        for (int g = 0; g < KPT / 2; g++) {
            float4 t = *(const float4*)(edT + j0 + kbase + 2 * g);
            ev[2*g]   = make_float2(t.x, t.y);
            ev[2*g+1] = make_float2(t.z, t.w);
        }
        float* pb = Ps + prow * PSROW + kbase;
#pragma unroll
        for (int u = 0; u < KPT; u++) {
            bool hot = (sv.x + dv[u]) > 0.f;
            float p = (hot ? sv.y : sv.z) * (hot ? ev[u].x : ev[u].y);
            p = ((aw >> u) & 1u) ? p : 0.f;
            p = tf32r(p);
            lsum += p;
            pb[u] = p;
        }
        __syncthreads();
    }

    for (int kt = 0; kt < NKT; kt++) {
        const int bb = kt & 1;
        const bool more = (kt + 1 < NKT);
        // ---- prefetch kt+1 into registers ----
        float4 wv[4]; float dv[KPT]; float2 ev[KPT]; unsigned aw = 0;
        if (more) {
            const int j0n = jbase + (kt + 1) * 32;
            const float* wp = Wh + (size_t)(j0n + jrow) * FH + fbase;
#pragma unroll
            for (int q = 0; q < 4; q++) wv[q] = *(const float4*)(wp + 64 * q);
            aw = adjrow[kt + 1] >> kbase;
#pragma unroll
            for (int g = 0; g < KPT / 4; g++) {
                float4 t = *(const float4*)(dR + j0n + kbase + 4 * g);
                dv[4*g] = t.x; dv[4*g+1] = t.y; dv[4*g+2] = t.z; dv[4*g+3] = t.w;
            }
#pragma unroll
            for (int g = 0; g < KPT / 2; g++) {
                float4 t = *(const float4*)(edT + j0n + kbase + 2 * g);
                ev[2*g]   = make_float2(t.x, t.y);
                ev[2*g+1] = make_float2(t.z, t.w);
            }
        }
        // ---- MMA on buffer bb ----
        const float* pB = Ps + bb * ROWS * PSROW;
        const float* wB = Whs + bb * 32 * WROW;
#pragma unroll
        for (int kk = 0; kk < 4; kk++) {
            const int k0 = kk * 8;
            uint32_t a[MT][4];
#pragma unroll
            for (int mt = 0; mt < MT; mt++) {
                const float* pr = pB + (wr * 16 * MT + mt * 16 + ar) * PSROW + k0 + ak;
                a[mt][0] = __float_as_uint(pr[0]);
                a[mt][1] = __float_as_uint(pr[8 * PSROW]);
                a[mt][2] = __float_as_uint(pr[4]);
                a[mt][3] = __float_as_uint(pr[8 * PSROW + 4]);
            }
#pragma unroll
            for (int nt = 0; nt < 8; nt++) {
                const int n = wc * 64 + nt * 8 + ar;
                uint32_t b0 = __float_as_uint(wB[(k0 + ak) * WROW + n]);
                uint32_t b1 = __float_as_uint(wB[(k0 + ak + 4) * WROW + n]);
#pragma unroll
                for (int mt = 0; mt < MT; mt++)
                    mma_tf32(d[mt][nt], a[mt], b0, b1);
            }
        }
        // ---- compute + STS kt+1 into buffer bb^1 ----
        if (more) {
            float* pb = Ps + (bb ^ 1) * ROWS * PSROW + prow * PSROW + kbase;
#pragma unroll
            for (int u = 0; u < KPT; u++) {
                bool hot = (sv.x + dv[u]) > 0.f;
                float p = (hot ? sv.y : sv.z) * (hot ? ev[u].x : ev[u].y);
                p = ((aw >> u) & 1u) ? p : 0.f;
                p = tf32r(p);
                lsum += p;
                pb[u] = p;
            }
            float* bs = Whs + (bb ^ 1) * 32 * WROW + jrow * WROW + fbase;
#pragma unroll
            for (int q = 0; q < 4; q++)
                *(float4*)(bs + 64 * q) =
                    make_float4(tf32r(wv[q].x), tf32r(wv[q].y),
                                tf32r(wv[q].z), tf32r(wv[q].w));
        }
        __syncthreads();
    }

    lpart[tid] = lsum;
    __syncthreads();

    if (PARTIAL) {
        float* np = g_np + (size_t)blockIdx.y * NV * FO;
#pragma unroll
        for (int mt = 0; mt < MT; mt++) {
            const int r0 = wr * 16 * MT + mt * 16 + ar;
            const int r1 = r0 + 8;
#pragma unroll
            for (int nt = 0; nt < 8; nt++) {
                const int c = wc * 64 + nt * 8 + 2 * ak;
                *(float2*)(np + (size_t)(i0 + r0) * FO + c) = make_float2(d[mt][nt][0], d[mt][nt][1]);
                *(float2*)(np + (size_t)(i0 + r1) * FO + c) = make_float2(d[mt][nt][2], d[mt][nt][3]);
            }
        }
        if (tid < ROWS) {
            float l = 0.f;
#pragma unroll
            for (int g = 0; g < PG; g++) l += lpart[tid * PG + g];
            g_lp[blockIdx.y * NV + i0 + tid] = l;
        }
    } else {
        float* out = g_h1;
        const int coloff = blockIdx.z * FH;
#pragma unroll
        for (int mt = 0; mt < MT; mt++) {
            const int r0 = wr * 16 * MT + mt * 16 + ar;
            const int r1 = r0 + 8;
            float l0 = 0.f, l1 = 0.f;
#pragma unroll
            for (int g = 0; g < PG; g++) {
                l0 += lpart[r0 * PG + g];
                l1 += lpart[r1 * PG + g];
            }
            const float rl0 = 1.0f / l0, rl1 = 1.0f / l1;
#pragma unroll
            for (int nt = 0; nt < 8; nt++) {
                const int c = coloff + wc * 64 + nt * 8 + 2 * ak;
                float o0 = d[mt][nt][0] * rl0, o1 = d[mt][nt][1] * rl0;
                float o2 = d[mt][nt][2] * rl1, o3 = d[mt][nt][3] * rl1;
                o0 = o0 > 0.f ? o0 : (__expf(o0) - 1.0f);
                o1 = o1 > 0.f ? o1 : (__expf(o1) - 1.0f);
                o2 = o2 > 0.f ? o2 : (__expf(o2) - 1.0f);
                o3 = o3 > 0.f ? o3 : (__expf(o3) - 1.0f);
                *(float2*)(out + (size_t)(i0 + r0) * F2 + c) = make_float2(o0, o1);
                *(float2*)(out + (size_t)(i0 + r1) * F2 + c) = make_float2(o2, o3);
            }
        }
    }
}

#define ATTN_SMEM(R) (2 * (R) * PSROW * 4 + 2 * 32 * WROW * 4 + 512 * 4)

// ---------------- K4: combine split partials (layer 1 epilogue) --------------
__global__ void combine_kernel(float* __restrict__ out) {
    const int i = blockIdx.x;
    const int c = threadIdx.x;
    const float l = g_lp[i] + g_lp[NV + i];
    const float n = g_np[(size_t)i * FO + c] +
                    g_np[(size_t)NV * FO + (size_t)i * FO + c];
    out[(size_t)i * FO + c] = n / l;
}

// ---------------- launch -----------------------------------------------------
extern "C" void kernel_launch(void* const* d_in, const int* in_sizes, int n_in,
                              void* d_out, int out_size) {
    (void)in_sizes; (void)n_in; (void)out_size;
    const float* x   = (const float*)d_in[0];
    const int*   adj = (const int*)d_in[1];
    const float* W1  = (const float*)d_in[2];
    const float* a1  = (const float*)d_in[3];
    const float* W2  = (const float*)d_in[4];
    const float* a2  = (const float*)d_in[5];
    float* out = (float*)d_out;

    static int inited = 0;
    if (!inited) {
        cudaFuncSetAttribute(gemm_tf32_kernel<128>,
            cudaFuncAttributeMaxDynamicSharedMemorySize, GEMM_SMEM(128));
        cudaFuncSetAttribute(gemm_tf32_kernel<64>,
            cudaFuncAttributeMaxDynamicSharedMemorySize, GEMM_SMEM(64));
        cudaFuncSetAttribute(attn_kernel<128, 0>,
            cudaFuncAttributeMaxDynamicSharedMemorySize, ATTN_SMEM(128));
        cudaFuncSetAttribute(attn_kernel<64, 1>,
            cudaFuncAttributeMaxDynamicSharedMemorySize, ATTN_SMEM(64));
        inited = 1;
    }

    float* Wh1p; cudaGetSymbolAddress((void**)&Wh1p, g_Wh1);
    float* h1p;  cudaGetSymbolAddress((void**)&h1p,  g_h1);
    float* Wh2p; cudaGetSymbolAddress((void**)&Wh2p, g_Wh2);

    adjbits_kernel<<<(NV * NV) / 256, 256>>>(adj);
    gemm_tf32_kernel<128><<<dim3(NV / 128, NHEADS), 512, GEMM_SMEM(128)>>>(
        x, W1, Wh1p, F1, (long)F1 * FH, (long)NV * FH);
    srcdst_kernel<<<dim3(NV / 8, NHEADS), 256>>>(a1, 0);
    attn_kernel<128, 0><<<dim3(NV / 128, 1, NHEADS), 512, ATTN_SMEM(128)>>>(nullptr);
    gemm_tf32_kernel<64><<<dim3(NV / 64, 1), 512, GEMM_SMEM(64)>>>(
        h1p, W2, Wh2p, F2, 0L, 0L);
    srcdst_kernel<<<dim3(NV / 8, 1), 256>>>(a2, 1);
    attn_kernel<64, 1><<<dim3(NV / 64, 2), 512, ATTN_SMEM(64)>>>(nullptr);
    combine_kernel<<<NV, 256>>>(out);
}